// round 5
// baseline (speedup 1.0000x reference)
#include <cuda_runtime.h>
#include <cstdint>

// Problem constants (fixed shapes per reference)
#define MAXN 50000
#define MAXE 800000
#define DIM  128
#define NH   8
#define HD   16

// ---------------- scratch (no allocations allowed) ----------------
__device__ __align__(16) float    g_q[MAXN * DIM];
__device__ __align__(16) float    g_k[MAXN * DIM];
__device__ __align__(16) float    g_v[MAXN * DIM];
__device__ __align__(16) float    g_agg[MAXN * DIM];
__device__ __align__(16) float    g_p[MAXE * NH];      // scores, then exp(p)
__device__ unsigned g_menc[MAXN * NH];                 // encoded segment max
__device__ float    g_s[MAXN * NH];                    // segment sum
__device__ int      g_is64;                            // edge_index dtype flag

// ---------------- helpers ----------------
__device__ __forceinline__ unsigned enc_f32(float x) {
    unsigned b = __float_as_uint(x);
    return (b & 0x80000000u) ? ~b : (b | 0x80000000u);
}
__device__ __forceinline__ float dec_f32(unsigned e) {
    return (e & 0x80000000u) ? __uint_as_float(e & 0x7FFFFFFFu)
                             : __uint_as_float(~e);
}

__device__ __forceinline__ int load_idx(const void* edge, int pos) {
    if (g_is64) return (int)__ldg(&((const long long*)edge)[pos]);
    return __ldg(&((const int*)edge)[pos]);
}

// ---------------- dtype detection ----------------
// int64 little-endian buffer of values in [0, 50000): every odd 32-bit word of
// the first 128 words is zero. Genuine int32 index data matches that with
// probability ~(1/50000)^64 ~= 0.
__global__ void detect_kernel(const int* __restrict__ e32) {
    if (threadIdx.x == 0 && blockIdx.x == 0) {
        int allzero = 1;
        for (int i = 1; i < 128; i += 2)
            if (e32[i] != 0) { allzero = 0; break; }
        g_is64 = allzero;
    }
}

// ---------------- zero-init ----------------
__global__ void zero_kernel(int n) {
    int i = blockIdx.x * blockDim.x + threadIdx.x;
    int stride = gridDim.x * blockDim.x;
    int nh = n * NH;
    for (int j = i; j < nh; j += stride) { g_menc[j] = 0u; g_s[j] = 0.0f; }
    int nd = n * DIM;
    for (int j = i; j < nd; j += stride) { g_agg[j] = 0.0f; }
}

// ---------------- SGEMM: Out[m][j] = sum_k X[m][k]*W[j][k] + b[j] ----------------
// BM=128, BN=128, BK=16, 256 threads, 8x8 micro-tile per thread.
__device__ __forceinline__ void gemm_body(const float* __restrict__ X,
                                          const float* __restrict__ W,
                                          const float* __restrict__ bias,
                                          float* __restrict__ Out, int n) {
    __shared__ float As[16][128];   // As[k][m] = X[row0+m][k0+k]
    __shared__ float Bs[16][128];   // Bs[k][j] = W[j][k0+k]

    const int row0 = blockIdx.x * 128;
    const int tid  = threadIdx.x;
    const int tr   = tid >> 4;      // 0..15 -> rows tr*8..tr*8+7
    const int tc   = tid & 15;      // 0..15 -> cols tc*8..tc*8+7

    float acc[8][8];
#pragma unroll
    for (int i = 0; i < 8; i++)
#pragma unroll
        for (int j = 0; j < 8; j++) acc[i][j] = 0.0f;

    for (int k0 = 0; k0 < DIM; k0 += 16) {
#pragma unroll
        for (int it = 0; it < 2; it++) {
            int t  = tid + it * 256;        // 0..511
            int m  = t >> 2;                // 0..127
            int kq = (t & 3) << 2;          // 0,4,8,12
            int gr = row0 + m;
            float4 va = make_float4(0.f, 0.f, 0.f, 0.f);
            if (gr < n)
                va = *reinterpret_cast<const float4*>(&X[(size_t)gr * DIM + k0 + kq]);
            As[kq + 0][m] = va.x; As[kq + 1][m] = va.y;
            As[kq + 2][m] = va.z; As[kq + 3][m] = va.w;

            float4 vb = __ldg(reinterpret_cast<const float4*>(&W[(size_t)m * DIM + k0 + kq]));
            Bs[kq + 0][m] = vb.x; Bs[kq + 1][m] = vb.y;
            Bs[kq + 2][m] = vb.z; Bs[kq + 3][m] = vb.w;
        }
        __syncthreads();

#pragma unroll
        for (int k = 0; k < 16; k++) {
            float a[8], b[8];
            float4 a0 = *reinterpret_cast<const float4*>(&As[k][tr * 8]);
            float4 a1 = *reinterpret_cast<const float4*>(&As[k][tr * 8 + 4]);
            float4 b0 = *reinterpret_cast<const float4*>(&Bs[k][tc * 8]);
            float4 b1 = *reinterpret_cast<const float4*>(&Bs[k][tc * 8 + 4]);
            a[0]=a0.x; a[1]=a0.y; a[2]=a0.z; a[3]=a0.w;
            a[4]=a1.x; a[5]=a1.y; a[6]=a1.z; a[7]=a1.w;
            b[0]=b0.x; b[1]=b0.y; b[2]=b0.z; b[3]=b0.w;
            b[4]=b1.x; b[5]=b1.y; b[6]=b1.z; b[7]=b1.w;
#pragma unroll
            for (int i = 0; i < 8; i++)
#pragma unroll
                for (int j = 0; j < 8; j++) acc[i][j] += a[i] * b[j];
        }
        __syncthreads();
    }

    float bb[8];
#pragma unroll
    for (int j = 0; j < 8; j++) bb[j] = __ldg(&bias[tc * 8 + j]);
#pragma unroll
    for (int i = 0; i < 8; i++) {
        int gr = row0 + tr * 8 + i;
        if (gr < n) {
            float4 o0 = make_float4(acc[i][0] + bb[0], acc[i][1] + bb[1],
                                    acc[i][2] + bb[2], acc[i][3] + bb[3]);
            float4 o1 = make_float4(acc[i][4] + bb[4], acc[i][5] + bb[5],
                                    acc[i][6] + bb[6], acc[i][7] + bb[7]);
            *reinterpret_cast<float4*>(&Out[(size_t)gr * DIM + tc * 8])     = o0;
            *reinterpret_cast<float4*>(&Out[(size_t)gr * DIM + tc * 8 + 4]) = o1;
        }
    }
}

__global__ __launch_bounds__(256)
void gemm_qkv_kernel(const float* __restrict__ x,
                     const float* __restrict__ Wq, const float* __restrict__ bq,
                     const float* __restrict__ Wk, const float* __restrict__ bk,
                     const float* __restrict__ Wv, const float* __restrict__ bv,
                     int n) {
    const float* W; const float* b; float* Out;
    if (blockIdx.y == 0)      { W = Wq; b = bq; Out = g_q; }
    else if (blockIdx.y == 1) { W = Wk; b = bk; Out = g_k; }
    else                      { W = Wv; b = bv; Out = g_v; }
    gemm_body(x, W, b, Out, n);
}

__global__ __launch_bounds__(256)
void gemm_out_kernel(const float* __restrict__ Wo, const float* __restrict__ bo,
                     float* __restrict__ out, int n) {
    gemm_body(g_agg, Wo, bo, out, n);
}

// ---------------- Pass A: edge scores + segment max ----------------
__global__ __launch_bounds__(256)
void scores_kernel(const void* __restrict__ edge, int E, int n) {
    int idx = blockIdx.x * blockDim.x + threadIdx.x;
    if (idx >= E * NH) return;
    int e = idx >> 3, h = idx & 7;
    int tgt = load_idx(edge, e);
    int src = load_idx(edge, E + e);
    if ((unsigned)tgt >= (unsigned)n || (unsigned)src >= (unsigned)n) return;
    const float4* qp = reinterpret_cast<const float4*>(&g_q[(size_t)src * DIM + h * HD]);
    const float4* kp = reinterpret_cast<const float4*>(&g_k[(size_t)tgt * DIM + h * HD]);
    float dot = 0.0f;
#pragma unroll
    for (int j = 0; j < 4; j++) {
        float4 a = qp[j], b = kp[j];
        dot += a.x * b.x + a.y * b.y + a.z * b.z + a.w * b.w;
    }
    float sc = dot * 0.25f;   // 1/sqrt(HD=16)
    g_p[idx] = sc;
    atomicMax(&g_menc[tgt * NH + h], enc_f32(sc));
}

// ---------------- Pass B: p = exp(score - m), segment sum ----------------
__global__ __launch_bounds__(256)
void pexp_kernel(const void* __restrict__ edge, int E, int n) {
    int idx = blockIdx.x * blockDim.x + threadIdx.x;
    if (idx >= E * NH) return;
    int e = idx >> 3, h = idx & 7;
    int tgt = load_idx(edge, e);
    if ((unsigned)tgt >= (unsigned)n) return;
    float m = dec_f32(g_menc[tgt * NH + h]);
    float p = expf(g_p[idx] - m);
    g_p[idx] = p;
    atomicAdd(&g_s[tgt * NH + h], p);
}

// ---------------- Pass C: agg[tgt] += (p/s) * v[src] ----------------
__global__ __launch_bounds__(256)
void agg_kernel(const void* __restrict__ edge, int E, int n) {
    int idx = blockIdx.x * blockDim.x + threadIdx.x;
    if (idx >= E * NH) return;
    int e = idx >> 3, h = idx & 7;
    int tgt = load_idx(edge, e);
    int src = load_idx(edge, E + e);
    if ((unsigned)tgt >= (unsigned)n || (unsigned)src >= (unsigned)n) return;
    float w = g_p[idx] / g_s[tgt * NH + h];
    const float4* vp = reinterpret_cast<const float4*>(&g_v[(size_t)src * DIM + h * HD]);
    float* ap = &g_agg[(size_t)tgt * DIM + h * HD];
#pragma unroll
    for (int j = 0; j < 4; j++) {
        float4 vv = vp[j];
        asm volatile("red.global.add.v4.f32 [%0], {%1, %2, %3, %4};"
                     :: "l"(ap + j * 4),
                        "f"(vv.x * w), "f"(vv.y * w), "f"(vv.z * w), "f"(vv.w * w)
                     : "memory");
    }
}

// ---------------- launch ----------------
extern "C" void kernel_launch(void* const* d_in, const int* in_sizes, int n_in,
                              void* d_out, int out_size) {
    const float* x    = (const float*)d_in[0];
    const void*  edge = d_in[1];
    const float* Wq   = (const float*)d_in[2];
    const float* bq   = (const float*)d_in[3];
    const float* Wk   = (const float*)d_in[4];
    const float* bk   = (const float*)d_in[5];
    const float* Wv   = (const float*)d_in[6];
    const float* bv   = (const float*)d_in[7];
    const float* Wo   = (const float*)d_in[8];
    const float* bo   = (const float*)d_in[9];
    float* out = (float*)d_out;

    int n = in_sizes[0] / DIM;
    int E = in_sizes[1] / 2;

    detect_kernel<<<1, 32>>>((const int*)edge);

    int zblocks = (n * DIM + 255) / 256;
    zero_kernel<<<zblocks, 256>>>(n);

    dim3 gqkv((n + 127) / 128, 3);
    gemm_qkv_kernel<<<gqkv, 256>>>(x, Wq, bq, Wk, bk, Wv, bv, n);

    int tot = E * NH;
    int eb = (tot + 255) / 256;
    scores_kernel<<<eb, 256>>>(edge, E, n);
    pexp_kernel<<<eb, 256>>>(edge, E, n);
    agg_kernel<<<eb, 256>>>(edge, E, n);

    gemm_out_kernel<<<(n + 127) / 128, 256>>>(Wo, bo, out, n);
}

// round 7
// speedup vs baseline: 1.0518x; 1.0518x over previous
#include <cuda_runtime.h>
#include <cstdint>

// Problem constants (fixed shapes per reference)
#define MAXN 50000
#define MAXE 800000
#define DIM  128
#define NH   8
#define HD   16

// ---------------- scratch (no allocations allowed) ----------------
__device__ __align__(16) float    g_q[MAXN * DIM];
__device__ __align__(16) float    g_k[MAXN * DIM];
__device__ __align__(16) float    g_v[MAXN * DIM];
__device__ __align__(16) float    g_agg[MAXN * DIM];
__device__ __align__(16) float    g_p[MAXE * NH];      // scores, then exp(p)
__device__ __align__(16) unsigned g_menc[MAXN * NH];   // encoded segment max
__device__ __align__(16) float    g_s[MAXN * NH];      // segment sum
__device__ int      g_tgt[MAXE];
__device__ int      g_src[MAXE];
__device__ int      g_is64;                            // edge_index dtype flag

// ---------------- helpers ----------------
__device__ __forceinline__ unsigned enc_f32(float x) {
    unsigned b = __float_as_uint(x);
    return (b & 0x80000000u) ? ~b : (b | 0x80000000u);
}
__device__ __forceinline__ float dec_f32(unsigned e) {
    return (e & 0x80000000u) ? __uint_as_float(e & 0x7FFFFFFFu)
                             : __uint_as_float(~e);
}
__device__ __forceinline__ void red_add_v4(float* p, float a, float b, float c, float d) {
    asm volatile("red.global.add.v4.f32 [%0], {%1, %2, %3, %4};"
                 :: "l"(p), "f"(a), "f"(b), "f"(c), "f"(d) : "memory");
}

// ---------------- dtype detection ----------------
// int64 little-endian buffer of values in [0, 50000): every odd 32-bit word of
// the first 128 words is zero. Genuine int32 index data matches that with
// probability ~(1/50000)^64 ~= 0.
__global__ void detect_kernel(const int* __restrict__ e32) {
    if (threadIdx.x == 0 && blockIdx.x == 0) {
        int allzero = 1;
        for (int i = 1; i < 128; i += 2)
            if (e32[i] != 0) { allzero = 0; break; }
        g_is64 = allzero;
    }
}

// ---------------- decode edge indices once ----------------
__global__ __launch_bounds__(256)
void prep_kernel(const void* __restrict__ edge, int E) {
    int e = blockIdx.x * blockDim.x + threadIdx.x;
    if (e >= E) return;
    int tgt, src;
    if (g_is64) {
        tgt = (int)__ldg(&((const long long*)edge)[e]);
        src = (int)__ldg(&((const long long*)edge)[E + e]);
    } else {
        tgt = __ldg(&((const int*)edge)[e]);
        src = __ldg(&((const int*)edge)[E + e]);
    }
    g_tgt[e] = tgt;
    g_src[e] = src;
}

// ---------------- zero-init ----------------
__global__ void zero_kernel(int n) {
    int i = blockIdx.x * blockDim.x + threadIdx.x;
    int stride = gridDim.x * blockDim.x;
    int nh = n * NH;
    for (int j = i; j < nh; j += stride) { g_menc[j] = 0u; g_s[j] = 0.0f; }
    int nd = n * DIM;
    for (int j = i; j < nd; j += stride) { g_agg[j] = 0.0f; }
}

// ---------------- SGEMM: Out[m][j] = sum_k X[m][k]*W[j][k] + b[j] ----------------
// BM=128, BN=128, BK=16, 256 threads, 8x8 micro-tile per thread.
__device__ __forceinline__ void gemm_body(const float* __restrict__ X,
                                          const float* __restrict__ W,
                                          const float* __restrict__ bias,
                                          float* __restrict__ Out, int n) {
    __shared__ float As[16][128];   // As[k][m] = X[row0+m][k0+k]
    __shared__ float Bs[16][128];   // Bs[k][j] = W[j][k0+k]

    const int row0 = blockIdx.x * 128;
    const int tid  = threadIdx.x;
    const int tr   = tid >> 4;
    const int tc   = tid & 15;

    float acc[8][8];
#pragma unroll
    for (int i = 0; i < 8; i++)
#pragma unroll
        for (int j = 0; j < 8; j++) acc[i][j] = 0.0f;

    for (int k0 = 0; k0 < DIM; k0 += 16) {
#pragma unroll
        for (int it = 0; it < 2; it++) {
            int t  = tid + it * 256;
            int m  = t >> 2;
            int kq = (t & 3) << 2;
            int gr = row0 + m;
            float4 va = make_float4(0.f, 0.f, 0.f, 0.f);
            if (gr < n)
                va = *reinterpret_cast<const float4*>(&X[(size_t)gr * DIM + k0 + kq]);
            As[kq + 0][m] = va.x; As[kq + 1][m] = va.y;
            As[kq + 2][m] = va.z; As[kq + 3][m] = va.w;

            float4 vb = __ldg(reinterpret_cast<const float4*>(&W[(size_t)m * DIM + k0 + kq]));
            Bs[kq + 0][m] = vb.x; Bs[kq + 1][m] = vb.y;
            Bs[kq + 2][m] = vb.z; Bs[kq + 3][m] = vb.w;
        }
        __syncthreads();

#pragma unroll
        for (int k = 0; k < 16; k++) {
            float a[8], b[8];
            float4 a0 = *reinterpret_cast<const float4*>(&As[k][tr * 8]);
            float4 a1 = *reinterpret_cast<const float4*>(&As[k][tr * 8 + 4]);
            float4 b0 = *reinterpret_cast<const float4*>(&Bs[k][tc * 8]);
            float4 b1 = *reinterpret_cast<const float4*>(&Bs[k][tc * 8 + 4]);
            a[0]=a0.x; a[1]=a0.y; a[2]=a0.z; a[3]=a0.w;
            a[4]=a1.x; a[5]=a1.y; a[6]=a1.z; a[7]=a1.w;
            b[0]=b0.x; b[1]=b0.y; b[2]=b0.z; b[3]=b0.w;
            b[4]=b1.x; b[5]=b1.y; b[6]=b1.z; b[7]=b1.w;
#pragma unroll
            for (int i = 0; i < 8; i++)
#pragma unroll
                for (int j = 0; j < 8; j++) acc[i][j] += a[i] * b[j];
        }
        __syncthreads();
    }

    float bb[8];
#pragma unroll
    for (int j = 0; j < 8; j++) bb[j] = __ldg(&bias[tc * 8 + j]);
#pragma unroll
    for (int i = 0; i < 8; i++) {
        int gr = row0 + tr * 8 + i;
        if (gr < n) {
            float4 o0 = make_float4(acc[i][0] + bb[0], acc[i][1] + bb[1],
                                    acc[i][2] + bb[2], acc[i][3] + bb[3]);
            float4 o1 = make_float4(acc[i][4] + bb[4], acc[i][5] + bb[5],
                                    acc[i][6] + bb[6], acc[i][7] + bb[7]);
            *reinterpret_cast<float4*>(&Out[(size_t)gr * DIM + tc * 8])     = o0;
            *reinterpret_cast<float4*>(&Out[(size_t)gr * DIM + tc * 8 + 4]) = o1;
        }
    }
}

__global__ __launch_bounds__(256)
void gemm_qkv_kernel(const float* __restrict__ x,
                     const float* __restrict__ Wq, const float* __restrict__ bq,
                     const float* __restrict__ Wk, const float* __restrict__ bk,
                     const float* __restrict__ Wv, const float* __restrict__ bv,
                     int n) {
    const float* W; const float* b; float* Out;
    if (blockIdx.y == 0)      { W = Wq; b = bq; Out = g_q; }
    else if (blockIdx.y == 1) { W = Wk; b = bk; Out = g_k; }
    else                      { W = Wv; b = bv; Out = g_v; }
    gemm_body(x, W, b, Out, n);
}

__global__ __launch_bounds__(256)
void gemm_out_kernel(const float* __restrict__ Wo, const float* __restrict__ bo,
                     float* __restrict__ out, int n) {
    gemm_body(g_agg, Wo, bo, out, n);
}

// ---------------- Pass A: warp-per-edge scores + segment max ----------------
// 32 lanes load full 512B q[src] and k[tgt] rows coalesced; 4-lane butterfly
// reduce yields the 8 head dots; lanes 0-7 write scores + atomicMax.
__global__ __launch_bounds__(256)
void scores_kernel(int E) {
    int w = (blockIdx.x * blockDim.x + threadIdx.x) >> 5;
    if (w >= E) return;
    int lane = threadIdx.x & 31;
    int tgt = g_tgt[w];
    int src = g_src[w];
    float4 qv = *reinterpret_cast<const float4*>(&g_q[(size_t)src * DIM + lane * 4]);
    float4 kv = *reinterpret_cast<const float4*>(&g_k[(size_t)tgt * DIM + lane * 4]);
    float part = qv.x * kv.x + qv.y * kv.y + qv.z * kv.z + qv.w * kv.w;
    part += __shfl_xor_sync(0xFFFFFFFFu, part, 1);
    part += __shfl_xor_sync(0xFFFFFFFFu, part, 2);
    // head h's dot now lives in lanes 4h..4h+3; gather to lanes 0..7
    float sc = __shfl_sync(0xFFFFFFFFu, part, lane * 4) * 0.25f; // *1/sqrt(16)
    if (lane < 8) {
        g_p[(size_t)w * NH + lane] = sc;
        atomicMax(&g_menc[tgt * NH + lane], enc_f32(sc));
    }
}

// ---------------- Pass B: thread-per-edge p = exp(sc - m), segment sum ----------------
__global__ __launch_bounds__(256)
void pexp_kernel(int E) {
    int e = blockIdx.x * blockDim.x + threadIdx.x;
    if (e >= E) return;
    int tgt = g_tgt[e];
    float4 s0 = *reinterpret_cast<const float4*>(&g_p[(size_t)e * NH]);
    float4 s1 = *reinterpret_cast<const float4*>(&g_p[(size_t)e * NH + 4]);
    uint4  m0 = *reinterpret_cast<const uint4*>(&g_menc[tgt * NH]);
    uint4  m1 = *reinterpret_cast<const uint4*>(&g_menc[tgt * NH + 4]);
    float4 p0, p1;
    p0.x = __expf(s0.x - dec_f32(m0.x));
    p0.y = __expf(s0.y - dec_f32(m0.y));
    p0.z = __expf(s0.z - dec_f32(m0.z));
    p0.w = __expf(s0.w - dec_f32(m0.w));
    p1.x = __expf(s1.x - dec_f32(m1.x));
    p1.y = __expf(s1.y - dec_f32(m1.y));
    p1.z = __expf(s1.z - dec_f32(m1.z));
    p1.w = __expf(s1.w - dec_f32(m1.w));
    *reinterpret_cast<float4*>(&g_p[(size_t)e * NH])     = p0;
    *reinterpret_cast<float4*>(&g_p[(size_t)e * NH + 4]) = p1;
    red_add_v4(&g_s[tgt * NH],     p0.x, p0.y, p0.z, p0.w);
    red_add_v4(&g_s[tgt * NH + 4], p1.x, p1.y, p1.z, p1.w);
}

// ---------------- Pass C: warp-per-edge agg[tgt] += (p/s) * v[src] ----------------
__global__ __launch_bounds__(256)
void agg_kernel(int E) {
    int w = (blockIdx.x * blockDim.x + threadIdx.x) >> 5;
    if (w >= E) return;
    int lane = threadIdx.x & 31;
    int tgt = g_tgt[w];
    int src = g_src[w];
    int h = lane >> 2;
    float weight = g_p[(size_t)w * NH + h] / g_s[tgt * NH + h];
    float4 vv = *reinterpret_cast<const float4*>(&g_v[(size_t)src * DIM + lane * 4]);
    red_add_v4(&g_agg[(size_t)tgt * DIM + lane * 4],
               vv.x * weight, vv.y * weight, vv.z * weight, vv.w * weight);
}

// ---------------- launch ----------------
extern "C" void kernel_launch(void* const* d_in, const int* in_sizes, int n_in,
                              void* d_out, int out_size) {
    const float* x    = (const float*)d_in[0];
    const void*  edge = d_in[1];
    const float* Wq   = (const float*)d_in[2];
    const float* bq   = (const float*)d_in[3];
    const float* Wk   = (const float*)d_in[4];
    const float* bk   = (const float*)d_in[5];
    const float* Wv   = (const float*)d_in[6];
    const float* bv   = (const float*)d_in[7];
    const float* Wo   = (const float*)d_in[8];
    const float* bo   = (const float*)d_in[9];
    float* out = (float*)d_out;

    int n = in_sizes[0] / DIM;
    int E = in_sizes[1] / 2;

    detect_kernel<<<1, 32>>>((const int*)edge);
    prep_kernel<<<(E + 255) / 256, 256>>>(edge, E);

    int zblocks = (n * DIM + 255) / 256;
    zero_kernel<<<zblocks, 256>>>(n);

    dim3 gqkv((n + 127) / 128, 3);
    gemm_qkv_kernel<<<gqkv, 256>>>(x, Wq, bq, Wk, bk, Wv, bv, n);

    // warp-per-edge kernels: 8 warps per 256-thread block
    int wb = (E + 7) / 8;
    scores_kernel<<<wb, 256>>>(E);
    pexp_kernel<<<(E + 255) / 256, 256>>>(E);
    agg_kernel<<<wb, 256>>>(E);

    gemm_out_kernel<<<(n + 127) / 128, 256>>>(Wo, bo, out, n);
}

// round 8
// speedup vs baseline: 1.3994x; 1.3305x over previous
#include <cuda_runtime.h>
#include <cstdint>
#include <cfloat>

// Problem constants (fixed shapes per reference)
#define MAXN 50000
#define MAXE 800000
#define DIM  128
#define NH   8
#define HD   16
#define FULLMASK 0xFFFFFFFFu

// ---------------- scratch (no allocations allowed) ----------------
__device__ __align__(16) float g_q[MAXN * DIM];
__device__ __align__(16) float g_k[MAXN * DIM];
__device__ __align__(16) float g_v[MAXN * DIM];
__device__ __align__(16) float g_agg[MAXN * DIM];
__device__ int g_tgt[MAXE];
__device__ int g_src[MAXE];
__device__ int g_ssrc[MAXE];       // src ids sorted by tgt
__device__ int g_cnt[MAXN + 1];    // per-target degree
__device__ int g_start[MAXN + 1];  // exclusive prefix of cnt
__device__ int g_cur[MAXN + 1];    // scatter cursors
__device__ int g_is64;             // edge_index dtype flag

// ---------------- dtype detection ----------------
// int64 little-endian buffer of values in [0, 50000): every odd 32-bit word of
// the first 128 words is zero. Genuine int32 index data matches that with
// probability ~(1/50000)^64 ~= 0.
__global__ void detect_kernel(const int* __restrict__ e32) {
    if (threadIdx.x == 0 && blockIdx.x == 0) {
        int allzero = 1;
        for (int i = 1; i < 128; i += 2)
            if (e32[i] != 0) { allzero = 0; break; }
        g_is64 = allzero;
    }
}

__global__ void zero_cnt_kernel(int n) {
    int i = blockIdx.x * blockDim.x + threadIdx.x;
    if (i <= n) g_cnt[i] = 0;
}

// ---------------- decode edges + histogram by target ----------------
__global__ __launch_bounds__(256)
void prep_kernel(const void* __restrict__ edge, int E, int n) {
    int e = blockIdx.x * blockDim.x + threadIdx.x;
    if (e >= E) return;
    int tgt, src;
    if (g_is64) {
        tgt = (int)__ldg(&((const long long*)edge)[e]);
        src = (int)__ldg(&((const long long*)edge)[E + e]);
    } else {
        tgt = __ldg(&((const int*)edge)[e]);
        src = __ldg(&((const int*)edge)[E + e]);
    }
    g_tgt[e] = tgt;
    g_src[e] = src;
    if ((unsigned)tgt < (unsigned)n && (unsigned)src < (unsigned)n)
        atomicAdd(&g_cnt[tgt], 1);
}

// ---------------- single-block exclusive scan over g_cnt[0..n) ----------------
__global__ __launch_bounds__(1024)
void scan_kernel(int n) {
    __shared__ int wsum[32];
    __shared__ int woff[32];
    __shared__ int btot;
    int tid = threadIdx.x, lane = tid & 31, wid = tid >> 5;
    int run = 0;
    for (int base = 0; base < n; base += 1024) {
        int i = base + tid;
        int v = (i < n) ? g_cnt[i] : 0;
        int x = v;
#pragma unroll
        for (int off = 1; off < 32; off <<= 1) {
            int t = __shfl_up_sync(FULLMASK, x, off);
            if (lane >= off) x += t;
        }
        if (lane == 31) wsum[wid] = x;
        __syncthreads();
        if (wid == 0) {
            int w = wsum[lane];
            int y = w;
#pragma unroll
            for (int off = 1; off < 32; off <<= 1) {
                int t = __shfl_up_sync(FULLMASK, y, off);
                if (lane >= off) y += t;
            }
            woff[lane] = y - w;
            if (lane == 31) btot = y;
        }
        __syncthreads();
        int excl = run + woff[wid] + x - v;
        if (i < n) { g_start[i] = excl; g_cur[i] = excl; }
        run += btot;
        __syncthreads();
    }
}

// ---------------- scatter edges into target-sorted order ----------------
__global__ __launch_bounds__(256)
void scatter_kernel(int E, int n) {
    int e = blockIdx.x * blockDim.x + threadIdx.x;
    if (e >= E) return;
    int tgt = g_tgt[e], src = g_src[e];
    if ((unsigned)tgt >= (unsigned)n || (unsigned)src >= (unsigned)n) return;
    int pos = atomicAdd(&g_cur[tgt], 1);
    g_ssrc[pos] = src;
}

// ---------------- SGEMM: Out[m][j] = sum_k X[m][k]*W[j][k] + b[j] ----------------
// BM=128, BN=128, BK=16, 256 threads, 8x8 micro-tile, register-prefetch
// double buffering: next tile's LDGs issue before the FFMA block.
__device__ __forceinline__ void gemm_body(const float* __restrict__ X,
                                          const float* __restrict__ W,
                                          const float* __restrict__ bias,
                                          float* __restrict__ Out, int n) {
    __shared__ float As[16][128];   // As[k][m] = X[row0+m][k0+k]
    __shared__ float Bs[16][128];   // Bs[k][j] = W[j][k0+k]

    const int row0 = blockIdx.x * 128;
    const int tid  = threadIdx.x;
    const int tr   = tid >> 4;
    const int tc   = tid & 15;

    float acc[8][8];
#pragma unroll
    for (int i = 0; i < 8; i++)
#pragma unroll
        for (int j = 0; j < 8; j++) acc[i][j] = 0.0f;

    float4 pa[2], pb[2];
#pragma unroll
    for (int it = 0; it < 2; it++) {
        int t  = tid + it * 256;
        int m  = t >> 2;
        int kq = (t & 3) << 2;
        int gr = row0 + m;
        pa[it] = (gr < n) ? *reinterpret_cast<const float4*>(&X[(size_t)gr * DIM + kq])
                          : make_float4(0.f, 0.f, 0.f, 0.f);
        pb[it] = __ldg(reinterpret_cast<const float4*>(&W[(size_t)m * DIM + kq]));
    }

    for (int k0 = 0; k0 < DIM; k0 += 16) {
#pragma unroll
        for (int it = 0; it < 2; it++) {
            int t  = tid + it * 256;
            int m  = t >> 2;
            int kq = (t & 3) << 2;
            As[kq + 0][m] = pa[it].x; As[kq + 1][m] = pa[it].y;
            As[kq + 2][m] = pa[it].z; As[kq + 3][m] = pa[it].w;
            Bs[kq + 0][m] = pb[it].x; Bs[kq + 1][m] = pb[it].y;
            Bs[kq + 2][m] = pb[it].z; Bs[kq + 3][m] = pb[it].w;
        }
        __syncthreads();

        if (k0 + 16 < DIM) {
#pragma unroll
            for (int it = 0; it < 2; it++) {
                int t  = tid + it * 256;
                int m  = t >> 2;
                int kq = (t & 3) << 2;
                int gr = row0 + m;
                pa[it] = (gr < n) ? *reinterpret_cast<const float4*>(&X[(size_t)gr * DIM + k0 + 16 + kq])
                                  : make_float4(0.f, 0.f, 0.f, 0.f);
                pb[it] = __ldg(reinterpret_cast<const float4*>(&W[(size_t)m * DIM + k0 + 16 + kq]));
            }
        }

#pragma unroll
        for (int k = 0; k < 16; k++) {
            float a[8], b[8];
            float4 a0 = *reinterpret_cast<const float4*>(&As[k][tr * 8]);
            float4 a1 = *reinterpret_cast<const float4*>(&As[k][tr * 8 + 4]);
            float4 b0 = *reinterpret_cast<const float4*>(&Bs[k][tc * 8]);
            float4 b1 = *reinterpret_cast<const float4*>(&Bs[k][tc * 8 + 4]);
            a[0]=a0.x; a[1]=a0.y; a[2]=a0.z; a[3]=a0.w;
            a[4]=a1.x; a[5]=a1.y; a[6]=a1.z; a[7]=a1.w;
            b[0]=b0.x; b[1]=b0.y; b[2]=b0.z; b[3]=b0.w;
            b[4]=b1.x; b[5]=b1.y; b[6]=b1.z; b[7]=b1.w;
#pragma unroll
            for (int i = 0; i < 8; i++)
#pragma unroll
                for (int j = 0; j < 8; j++) acc[i][j] += a[i] * b[j];
        }
        __syncthreads();
    }

    float bb[8];
#pragma unroll
    for (int j = 0; j < 8; j++) bb[j] = __ldg(&bias[tc * 8 + j]);
#pragma unroll
    for (int i = 0; i < 8; i++) {
        int gr = row0 + tr * 8 + i;
        if (gr < n) {
            float4 o0 = make_float4(acc[i][0] + bb[0], acc[i][1] + bb[1],
                                    acc[i][2] + bb[2], acc[i][3] + bb[3]);
            float4 o1 = make_float4(acc[i][4] + bb[4], acc[i][5] + bb[5],
                                    acc[i][6] + bb[6], acc[i][7] + bb[7]);
            *reinterpret_cast<float4*>(&Out[(size_t)gr * DIM + tc * 8])     = o0;
            *reinterpret_cast<float4*>(&Out[(size_t)gr * DIM + tc * 8 + 4]) = o1;
        }
    }
}

__global__ __launch_bounds__(256, 2)
void gemm_qkv_kernel(const float* __restrict__ x,
                     const float* __restrict__ Wq, const float* __restrict__ bq,
                     const float* __restrict__ Wk, const float* __restrict__ bk,
                     const float* __restrict__ Wv, const float* __restrict__ bv,
                     int n) {
    const float* W; const float* b; float* Out;
    if (blockIdx.y == 0)      { W = Wq; b = bq; Out = g_q; }
    else if (blockIdx.y == 1) { W = Wk; b = bk; Out = g_k; }
    else                      { W = Wv; b = bv; Out = g_v; }
    gemm_body(x, W, b, Out, n);
}

__global__ __launch_bounds__(256, 2)
void gemm_out_kernel(const float* __restrict__ Wo, const float* __restrict__ bo,
                     float* __restrict__ out, int n) {
    gemm_body(g_agg, Wo, bo, out, n);
}

// ---------------- fused attention: warp per target node ----------------
// k[tgt] held in registers; single pass over the node's (sorted) edges with
// online softmax; agg[tgt] written once, normalized. No atomics.
__global__ __launch_bounds__(256)
void attn_kernel(int n) {
    int node = (blockIdx.x * blockDim.x + threadIdx.x) >> 5;
    if (node >= n) return;
    int lane = threadIdx.x & 31;

    int start = g_start[node];
    int cnt   = g_cnt[node];

    // lane covers dims [lane*4, lane*4+4) => head h = lane>>2
    float4 kv = *reinterpret_cast<const float4*>(&g_k[(size_t)node * DIM + lane * 4]);

    float m = -FLT_MAX, sum = 0.0f;
    float ax = 0.f, ay = 0.f, az = 0.f, aw = 0.f;

    for (int base = 0; base < cnt; base += 32) {
        int myi = base + lane;
        int src_l = (myi < cnt) ? g_ssrc[start + myi] : 0;
        int lim = min(32, cnt - base);
        int j = 0;
        for (; j + 4 <= lim; j += 4) {
            float s[4]; float4 vv[4];
#pragma unroll
            for (int u = 0; u < 4; u++) {
                int src = __shfl_sync(FULLMASK, src_l, j + u);
                float4 qv = *reinterpret_cast<const float4*>(&g_q[(size_t)src * DIM + lane * 4]);
                vv[u]     = *reinterpret_cast<const float4*>(&g_v[(size_t)src * DIM + lane * 4]);
                float part = qv.x * kv.x + qv.y * kv.y + qv.z * kv.z + qv.w * kv.w;
                part += __shfl_xor_sync(FULLMASK, part, 1);
                part += __shfl_xor_sync(FULLMASK, part, 2);
                s[u] = part * 0.25f;    // 1/sqrt(HD=16)
            }
#pragma unroll
            for (int u = 0; u < 4; u++) {
                float nm = fmaxf(m, s[u]);
                float f  = __expf(m - nm);
                float p  = __expf(s[u] - nm);
                sum = sum * f + p;
                ax = ax * f + p * vv[u].x;
                ay = ay * f + p * vv[u].y;
                az = az * f + p * vv[u].z;
                aw = aw * f + p * vv[u].w;
                m = nm;
            }
        }
        for (; j < lim; j++) {
            int src = __shfl_sync(FULLMASK, src_l, j);
            float4 qv = *reinterpret_cast<const float4*>(&g_q[(size_t)src * DIM + lane * 4]);
            float4 vv = *reinterpret_cast<const float4*>(&g_v[(size_t)src * DIM + lane * 4]);
            float part = qv.x * kv.x + qv.y * kv.y + qv.z * kv.z + qv.w * kv.w;
            part += __shfl_xor_sync(FULLMASK, part, 1);
            part += __shfl_xor_sync(FULLMASK, part, 2);
            float s = part * 0.25f;
            float nm = fmaxf(m, s);
            float f  = __expf(m - nm);
            float p  = __expf(s - nm);
            sum = sum * f + p;
            ax = ax * f + p * vv.x;
            ay = ay * f + p * vv.y;
            az = az * f + p * vv.z;
            aw = aw * f + p * vv.w;
            m = nm;
        }
    }

    float inv = (sum > 0.0f) ? 1.0f / sum : 0.0f;
    float4 o = make_float4(ax * inv, ay * inv, az * inv, aw * inv);
    *reinterpret_cast<float4*>(&g_agg[(size_t)node * DIM + lane * 4]) = o;
}

// ---------------- launch ----------------
extern "C" void kernel_launch(void* const* d_in, const int* in_sizes, int n_in,
                              void* d_out, int out_size) {
    const float* x    = (const float*)d_in[0];
    const void*  edge = d_in[1];
    const float* Wq   = (const float*)d_in[2];
    const float* bq   = (const float*)d_in[3];
    const float* Wk   = (const float*)d_in[4];
    const float* bk   = (const float*)d_in[5];
    const float* Wv   = (const float*)d_in[6];
    const float* bv   = (const float*)d_in[7];
    const float* Wo   = (const float*)d_in[8];
    const float* bo   = (const float*)d_in[9];
    float* out = (float*)d_out;

    int n = in_sizes[0] / DIM;
    int E = in_sizes[1] / 2;

    detect_kernel<<<1, 32>>>((const int*)edge);
    zero_cnt_kernel<<<(n + 256) / 256, 256>>>(n);
    prep_kernel<<<(E + 255) / 256, 256>>>(edge, E, n);
    scan_kernel<<<1, 1024>>>(n);
    scatter_kernel<<<(E + 255) / 256, 256>>>(E, n);

    dim3 gqkv((n + 127) / 128, 3);
    gemm_qkv_kernel<<<gqkv, 256>>>(x, Wq, bq, Wk, bk, Wv, bv, n);

    attn_kernel<<<(n + 7) / 8, 256>>>(n);

    gemm_out_kernel<<<(n + 127) / 128, 256>>>(Wo, bo, out, n);
}

// round 9
// speedup vs baseline: 1.5712x; 1.1228x over previous
#include <cuda_runtime.h>
#include <cstdint>
#include <cfloat>

// Problem constants (fixed shapes per reference)
#define MAXN 50000
#define MAXE 800000
#define DIM  128
#define NH   8
#define HD   16
#define FULLMASK 0xFFFFFFFFu
#define SCAN_BLK 1024
#define MAX_SBLOCKS 64   // ceil(50000/1024)=49

// ---------------- scratch (no allocations allowed) ----------------
__device__ __align__(16) float g_q[MAXN * DIM];
__device__ __align__(16) float g_k[MAXN * DIM];
__device__ __align__(16) float g_v[MAXN * DIM];
__device__ __align__(16) float g_agg[MAXN * DIM];
__device__ int g_tgt[MAXE];
__device__ int g_src[MAXE];
__device__ int g_ssrc[MAXE];       // src ids sorted by tgt
__device__ int g_cnt[MAXN + 1];    // per-target degree
__device__ int g_start[MAXN + 1];  // exclusive prefix of cnt
__device__ int g_cur[MAXN + 1];    // scatter cursors
__device__ int g_bsum[MAX_SBLOCKS];
__device__ int g_boff[MAX_SBLOCKS];
__device__ int g_is64;             // edge_index dtype flag

// ---------------- dtype detection ----------------
// int64 little-endian buffer of values in [0, 50000): every odd 32-bit word of
// the first 128 words is zero. Genuine int32 index data matches that with
// probability ~(1/50000)^64 ~= 0.
__global__ void detect_kernel(const int* __restrict__ e32) {
    if (threadIdx.x == 0 && blockIdx.x == 0) {
        int allzero = 1;
        for (int i = 1; i < 128; i += 2)
            if (e32[i] != 0) { allzero = 0; break; }
        g_is64 = allzero;
    }
}

__global__ void zero_cnt_kernel(int n) {
    int i = blockIdx.x * blockDim.x + threadIdx.x;
    if (i <= n) g_cnt[i] = 0;
}

// ---------------- decode edges + histogram by target ----------------
__global__ __launch_bounds__(256)
void prep_kernel(const void* __restrict__ edge, int E, int n) {
    int e = blockIdx.x * blockDim.x + threadIdx.x;
    if (e >= E) return;
    int tgt, src;
    if (g_is64) {
        tgt = (int)__ldg(&((const long long*)edge)[e]);
        src = (int)__ldg(&((const long long*)edge)[E + e]);
    } else {
        tgt = __ldg(&((const int*)edge)[e]);
        src = __ldg(&((const int*)edge)[E + e]);
    }
    g_tgt[e] = tgt;
    g_src[e] = src;
    if ((unsigned)tgt < (unsigned)n && (unsigned)src < (unsigned)n)
        atomicAdd(&g_cnt[tgt], 1);
}

// ---------------- multi-block exclusive scan of g_cnt[0..n) ----------------
// Phase 1: per-block local exclusive scan + block total.
__global__ __launch_bounds__(SCAN_BLK)
void scan1_kernel(int n) {
    __shared__ int wsum[32];
    __shared__ int woff[32];
    int tid = threadIdx.x, lane = tid & 31, wid = tid >> 5;
    int i = blockIdx.x * SCAN_BLK + tid;
    int v = (i < n) ? g_cnt[i] : 0;
    int x = v;
#pragma unroll
    for (int off = 1; off < 32; off <<= 1) {
        int t = __shfl_up_sync(FULLMASK, x, off);
        if (lane >= off) x += t;
    }
    if (lane == 31) wsum[wid] = x;
    __syncthreads();
    if (wid == 0) {
        int w = wsum[lane];
        int y = w;
#pragma unroll
        for (int off = 1; off < 32; off <<= 1) {
            int t = __shfl_up_sync(FULLMASK, y, off);
            if (lane >= off) y += t;
        }
        woff[lane] = y - w;
        if (lane == 31) g_bsum[blockIdx.x] = y;
    }
    __syncthreads();
    if (i < n) g_start[i] = woff[wid] + x - v;
}

// Phase 2: one warp scans the block totals (<= MAX_SBLOCKS).
__global__ void scan2_kernel(int nblocks) {
    int lane = threadIdx.x;   // 64 threads
    int v = (lane < nblocks) ? g_bsum[lane] : 0;
    // exclusive scan over 64 via two-warp trick: just do it serially in shared
    __shared__ int sh[MAX_SBLOCKS];
    if (lane < MAX_SBLOCKS) sh[lane] = v;
    __syncthreads();
    if (lane == 0) {
        int run = 0;
        for (int j = 0; j < nblocks; j++) { int t = sh[j]; sh[j] = run; run += t; }
    }
    __syncthreads();
    if (lane < nblocks) g_boff[lane] = sh[lane];
}

// Phase 3: add block offsets, init cursors.
__global__ __launch_bounds__(SCAN_BLK)
void scan3_kernel(int n) {
    int i = blockIdx.x * SCAN_BLK + threadIdx.x;
    if (i < n) {
        int s = g_start[i] + g_boff[blockIdx.x];
        g_start[i] = s;
        g_cur[i]   = s;
    }
}

// ---------------- scatter edges into target-sorted order ----------------
__global__ __launch_bounds__(256)
void scatter_kernel(int E, int n) {
    int e = blockIdx.x * blockDim.x + threadIdx.x;
    if (e >= E) return;
    int tgt = g_tgt[e], src = g_src[e];
    if ((unsigned)tgt >= (unsigned)n || (unsigned)src >= (unsigned)n) return;
    int pos = atomicAdd(&g_cur[tgt], 1);
    g_ssrc[pos] = src;
}

// ---------------- SGEMM: Out[m][j] = sum_k X[m][k]*W[j][k] + b[j] ----------------
// BM=128, BN=128, BK=16, 256 threads, 8x8 micro-tile, register-prefetch
// double buffering: next tile's LDGs issue before the FFMA block.
__device__ __forceinline__ void gemm_body(const float* __restrict__ X,
                                          const float* __restrict__ W,
                                          const float* __restrict__ bias,
                                          float* __restrict__ Out, int n) {
    __shared__ float As[16][128];   // As[k][m] = X[row0+m][k0+k]
    __shared__ float Bs[16][128];   // Bs[k][j] = W[j][k0+k]

    const int row0 = blockIdx.x * 128;
    const int tid  = threadIdx.x;
    const int tr   = tid >> 4;
    const int tc   = tid & 15;

    float acc[8][8];
#pragma unroll
    for (int i = 0; i < 8; i++)
#pragma unroll
        for (int j = 0; j < 8; j++) acc[i][j] = 0.0f;

    float4 pa[2], pb[2];
#pragma unroll
    for (int it = 0; it < 2; it++) {
        int t  = tid + it * 256;
        int m  = t >> 2;
        int kq = (t & 3) << 2;
        int gr = row0 + m;
        pa[it] = (gr < n) ? *reinterpret_cast<const float4*>(&X[(size_t)gr * DIM + kq])
                          : make_float4(0.f, 0.f, 0.f, 0.f);
        pb[it] = __ldg(reinterpret_cast<const float4*>(&W[(size_t)m * DIM + kq]));
    }

    for (int k0 = 0; k0 < DIM; k0 += 16) {
#pragma unroll
        for (int it = 0; it < 2; it++) {
            int t  = tid + it * 256;
            int m  = t >> 2;
            int kq = (t & 3) << 2;
            As[kq + 0][m] = pa[it].x; As[kq + 1][m] = pa[it].y;
            As[kq + 2][m] = pa[it].z; As[kq + 3][m] = pa[it].w;
            Bs[kq + 0][m] = pb[it].x; Bs[kq + 1][m] = pb[it].y;
            Bs[kq + 2][m] = pb[it].z; Bs[kq + 3][m] = pb[it].w;
        }
        __syncthreads();

        if (k0 + 16 < DIM) {
#pragma unroll
            for (int it = 0; it < 2; it++) {
                int t  = tid + it * 256;
                int m  = t >> 2;
                int kq = (t & 3) << 2;
                int gr = row0 + m;
                pa[it] = (gr < n) ? *reinterpret_cast<const float4*>(&X[(size_t)gr * DIM + k0 + 16 + kq])
                                  : make_float4(0.f, 0.f, 0.f, 0.f);
                pb[it] = __ldg(reinterpret_cast<const float4*>(&W[(size_t)m * DIM + k0 + 16 + kq]));
            }
        }

#pragma unroll
        for (int k = 0; k < 16; k++) {
            float a[8], b[8];
            float4 a0 = *reinterpret_cast<const float4*>(&As[k][tr * 8]);
            float4 a1 = *reinterpret_cast<const float4*>(&As[k][tr * 8 + 4]);
            float4 b0 = *reinterpret_cast<const float4*>(&Bs[k][tc * 8]);
            float4 b1 = *reinterpret_cast<const float4*>(&Bs[k][tc * 8 + 4]);
            a[0]=a0.x; a[1]=a0.y; a[2]=a0.z; a[3]=a0.w;
            a[4]=a1.x; a[5]=a1.y; a[6]=a1.z; a[7]=a1.w;
            b[0]=b0.x; b[1]=b0.y; b[2]=b0.z; b[3]=b0.w;
            b[4]=b1.x; b[5]=b1.y; b[6]=b1.z; b[7]=b1.w;
#pragma unroll
            for (int i = 0; i < 8; i++)
#pragma unroll
                for (int j = 0; j < 8; j++) acc[i][j] += a[i] * b[j];
        }
        __syncthreads();
    }

    float bb[8];
#pragma unroll
    for (int j = 0; j < 8; j++) bb[j] = __ldg(&bias[tc * 8 + j]);
#pragma unroll
    for (int i = 0; i < 8; i++) {
        int gr = row0 + tr * 8 + i;
        if (gr < n) {
            float4 o0 = make_float4(acc[i][0] + bb[0], acc[i][1] + bb[1],
                                    acc[i][2] + bb[2], acc[i][3] + bb[3]);
            float4 o1 = make_float4(acc[i][4] + bb[4], acc[i][5] + bb[5],
                                    acc[i][6] + bb[6], acc[i][7] + bb[7]);
            *reinterpret_cast<float4*>(&Out[(size_t)gr * DIM + tc * 8])     = o0;
            *reinterpret_cast<float4*>(&Out[(size_t)gr * DIM + tc * 8 + 4]) = o1;
        }
    }
}

__global__ __launch_bounds__(256, 2)
void gemm_qkv_kernel(const float* __restrict__ x,
                     const float* __restrict__ Wq, const float* __restrict__ bq,
                     const float* __restrict__ Wk, const float* __restrict__ bk,
                     const float* __restrict__ Wv, const float* __restrict__ bv,
                     int n) {
    const float* W; const float* b; float* Out;
    if (blockIdx.y == 0)      { W = Wq; b = bq; Out = g_q; }
    else if (blockIdx.y == 1) { W = Wk; b = bk; Out = g_k; }
    else                      { W = Wv; b = bv; Out = g_v; }
    gemm_body(x, W, b, Out, n);
}

__global__ __launch_bounds__(256, 2)
void gemm_out_kernel(const float* __restrict__ Wo, const float* __restrict__ bo,
                     float* __restrict__ out, int n) {
    gemm_body(g_agg, Wo, bo, out, n);
}

// ---------------- fused attention: warp per target node ----------------
// k[tgt] held in registers; single pass over the node's (sorted) edges with
// online softmax; agg[tgt] written once, normalized. No atomics.
__global__ __launch_bounds__(256)
void attn_kernel(int n) {
    int node = (blockIdx.x * blockDim.x + threadIdx.x) >> 5;
    if (node >= n) return;
    int lane = threadIdx.x & 31;

    int start = g_start[node];
    int cnt   = g_cnt[node];

    // lane covers dims [lane*4, lane*4+4) => head h = lane>>2
    float4 kv = *reinterpret_cast<const float4*>(&g_k[(size_t)node * DIM + lane * 4]);

    float m = -FLT_MAX, sum = 0.0f;
    float ax = 0.f, ay = 0.f, az = 0.f, aw = 0.f;

    for (int base = 0; base < cnt; base += 32) {
        int myi = base + lane;
        int src_l = (myi < cnt) ? g_ssrc[start + myi] : 0;
        int lim = min(32, cnt - base);
        int j = 0;
        for (; j + 4 <= lim; j += 4) {
            float s[4]; float4 vv[4];
#pragma unroll
            for (int u = 0; u < 4; u++) {
                int src = __shfl_sync(FULLMASK, src_l, j + u);
                float4 qv = *reinterpret_cast<const float4*>(&g_q[(size_t)src * DIM + lane * 4]);
                vv[u]     = *reinterpret_cast<const float4*>(&g_v[(size_t)src * DIM + lane * 4]);
                float part = qv.x * kv.x + qv.y * kv.y + qv.z * kv.z + qv.w * kv.w;
                part += __shfl_xor_sync(FULLMASK, part, 1);
                part += __shfl_xor_sync(FULLMASK, part, 2);
                s[u] = part * 0.25f;    // 1/sqrt(HD=16)
            }
#pragma unroll
            for (int u = 0; u < 4; u++) {
                float nm = fmaxf(m, s[u]);
                float f  = __expf(m - nm);
                float p  = __expf(s[u] - nm);
                sum = sum * f + p;
                ax = ax * f + p * vv[u].x;
                ay = ay * f + p * vv[u].y;
                az = az * f + p * vv[u].z;
                aw = aw * f + p * vv[u].w;
                m = nm;
            }
        }
        for (; j < lim; j++) {
            int src = __shfl_sync(FULLMASK, src_l, j);
            float4 qv = *reinterpret_cast<const float4*>(&g_q[(size_t)src * DIM + lane * 4]);
            float4 vv = *reinterpret_cast<const float4*>(&g_v[(size_t)src * DIM + lane * 4]);
            float part = qv.x * kv.x + qv.y * kv.y + qv.z * kv.z + qv.w * kv.w;
            part += __shfl_xor_sync(FULLMASK, part, 1);
            part += __shfl_xor_sync(FULLMASK, part, 2);
            float s = part * 0.25f;
            float nm = fmaxf(m, s);
            float f  = __expf(m - nm);
            float p  = __expf(s - nm);
            sum = sum * f + p;
            ax = ax * f + p * vv.x;
            ay = ay * f + p * vv.y;
            az = az * f + p * vv.z;
            aw = aw * f + p * vv.w;
            m = nm;
        }
    }

    float inv = (sum > 0.0f) ? 1.0f / sum : 0.0f;
    float4 o = make_float4(ax * inv, ay * inv, az * inv, aw * inv);
    *reinterpret_cast<float4*>(&g_agg[(size_t)node * DIM + lane * 4]) = o;
}

// ---------------- launch ----------------
extern "C" void kernel_launch(void* const* d_in, const int* in_sizes, int n_in,
                              void* d_out, int out_size) {
    const float* x    = (const float*)d_in[0];
    const void*  edge = d_in[1];
    const float* Wq   = (const float*)d_in[2];
    const float* bq   = (const float*)d_in[3];
    const float* Wk   = (const float*)d_in[4];
    const float* bk   = (const float*)d_in[5];
    const float* Wv   = (const float*)d_in[6];
    const float* bv   = (const float*)d_in[7];
    const float* Wo   = (const float*)d_in[8];
    const float* bo   = (const float*)d_in[9];
    float* out = (float*)d_out;

    int n = in_sizes[0] / DIM;
    int E = in_sizes[1] / 2;

    int sblocks = (n + SCAN_BLK - 1) / SCAN_BLK;   // <= MAX_SBLOCKS

    detect_kernel<<<1, 32>>>((const int*)edge);
    zero_cnt_kernel<<<(n + 256) / 256, 256>>>(n);
    prep_kernel<<<(E + 255) / 256, 256>>>(edge, E, n);
    scan1_kernel<<<sblocks, SCAN_BLK>>>(n);
    scan2_kernel<<<1, 64>>>(sblocks);
    scan3_kernel<<<sblocks, SCAN_BLK>>>(n);
    scatter_kernel<<<(E + 255) / 256, 256>>>(E, n);

    dim3 gqkv((n + 127) / 128, 3);
    gemm_qkv_kernel<<<gqkv, 256>>>(x, Wq, bq, Wk, bk, Wv, bv, n);

    attn_kernel<<<(n + 7) / 8, 256>>>(n);

    gemm_out_kernel<<<(n + 127) / 128, 256>>>(Wo, bo, out, n);
}

// round 11
// speedup vs baseline: 1.6022x; 1.0197x over previous
#include <cuda_runtime.h>
#include <cstdint>
#include <cfloat>

// Problem constants (fixed shapes per reference)
#define MAXN 50000
#define MAXE 800000
#define DIM  128
#define NH   8
#define HD   16
#define FULLMASK 0xFFFFFFFFu
#define SCAN_BLK 1024
#define MAX_SBLOCKS 64   // ceil(50000/1024)=49

// ---------------- scratch (no allocations allowed) ----------------
__device__ __align__(16) float g_q[MAXN * DIM];
__device__ __align__(16) float g_k[MAXN * DIM];
__device__ __align__(16) float g_v[MAXN * DIM];
__device__ __align__(16) float g_agg[MAXN * DIM];
__device__ int g_tgt[MAXE];
__device__ int g_src[MAXE];
__device__ int g_ssrc[MAXE];       // src ids sorted by tgt
__device__ int g_cnt[MAXN + 1];    // per-target degree
__device__ int g_start[MAXN + 1];  // exclusive prefix of cnt
__device__ int g_cur[MAXN + 1];    // scatter cursors
__device__ int g_bsum[MAX_SBLOCKS];
__device__ int g_boff[MAX_SBLOCKS];
__device__ int g_is64;             // edge_index dtype flag

// ---------------- dtype detection ----------------
// int64 little-endian buffer of values in [0, 50000): every odd 32-bit word of
// the first 128 words is zero. Genuine int32 index data matches that with
// probability ~(1/50000)^64 ~= 0.
__global__ void detect_kernel(const int* __restrict__ e32) {
    if (threadIdx.x == 0 && blockIdx.x == 0) {
        int allzero = 1;
        for (int i = 1; i < 128; i += 2)
            if (e32[i] != 0) { allzero = 0; break; }
        g_is64 = allzero;
    }
}

__global__ void zero_cnt_kernel(int n) {
    int i = blockIdx.x * blockDim.x + threadIdx.x;
    if (i <= n) g_cnt[i] = 0;
}

// ---------------- decode edges + histogram by target ----------------
__global__ __launch_bounds__(256)
void prep_kernel(const void* __restrict__ edge, int E, int n) {
    int e = blockIdx.x * blockDim.x + threadIdx.x;
    if (e >= E) return;
    int tgt, src;
    if (g_is64) {
        tgt = (int)__ldg(&((const long long*)edge)[e]);
        src = (int)__ldg(&((const long long*)edge)[E + e]);
    } else {
        tgt = __ldg(&((const int*)edge)[e]);
        src = __ldg(&((const int*)edge)[E + e]);
    }
    g_tgt[e] = tgt;
    g_src[e] = src;
    if ((unsigned)tgt < (unsigned)n && (unsigned)src < (unsigned)n)
        atomicAdd(&g_cnt[tgt], 1);
}

// ---------------- multi-block exclusive scan of g_cnt[0..n) ----------------
__global__ __launch_bounds__(SCAN_BLK)
void scan1_kernel(int n) {
    __shared__ int wsum[32];
    __shared__ int woff[32];
    int tid = threadIdx.x, lane = tid & 31, wid = tid >> 5;
    int i = blockIdx.x * SCAN_BLK + tid;
    int v = (i < n) ? g_cnt[i] : 0;
    int x = v;
#pragma unroll
    for (int off = 1; off < 32; off <<= 1) {
        int t = __shfl_up_sync(FULLMASK, x, off);
        if (lane >= off) x += t;
    }
    if (lane == 31) wsum[wid] = x;
    __syncthreads();
    if (wid == 0) {
        int w = wsum[lane];
        int y = w;
#pragma unroll
        for (int off = 1; off < 32; off <<= 1) {
            int t = __shfl_up_sync(FULLMASK, y, off);
            if (lane >= off) y += t;
        }
        woff[lane] = y - w;
        if (lane == 31) g_bsum[blockIdx.x] = y;
    }
    __syncthreads();
    if (i < n) g_start[i] = woff[wid] + x - v;
}

__global__ void scan2_kernel(int nblocks) {
    int lane = threadIdx.x;
    __shared__ int sh[MAX_SBLOCKS];
    if (lane < MAX_SBLOCKS) sh[lane] = (lane < nblocks) ? g_bsum[lane] : 0;
    __syncthreads();
    if (lane == 0) {
        int run = 0;
        for (int j = 0; j < nblocks; j++) { int t = sh[j]; sh[j] = run; run += t; }
    }
    __syncthreads();
    if (lane < nblocks) g_boff[lane] = sh[lane];
}

__global__ __launch_bounds__(SCAN_BLK)
void scan3_kernel(int n) {
    int i = blockIdx.x * SCAN_BLK + threadIdx.x;
    if (i < n) {
        int s = g_start[i] + g_boff[blockIdx.x];
        g_start[i] = s;
        g_cur[i]   = s;
    }
}

// ---------------- scatter edges into target-sorted order ----------------
__global__ __launch_bounds__(256)
void scatter_kernel(int E, int n) {
    int e = blockIdx.x * blockDim.x + threadIdx.x;
    if (e >= E) return;
    int tgt = g_tgt[e], src = g_src[e];
    if ((unsigned)tgt >= (unsigned)n || (unsigned)src >= (unsigned)n) return;
    int pos = atomicAdd(&g_cur[tgt], 1);
    g_ssrc[pos] = src;
}

// ---------------- SGEMM: Out[m][j] = sum_k X[m][k]*W[j][k] + b[j] ----------------
// BM=128, BN=128, BK=16, 256 threads, 8x8 micro-tile, register-prefetch
// double buffering: next tile's LDGs issue before the FFMA block.
__device__ __forceinline__ void gemm_body(const float* __restrict__ X,
                                          const float* __restrict__ W,
                                          const float* __restrict__ bias,
                                          float* __restrict__ Out, int n) {
    __shared__ float As[16][128];   // As[k][m] = X[row0+m][k0+k]
    __shared__ float Bs[16][128];   // Bs[k][j] = W[j][k0+k]

    const int row0 = blockIdx.x * 128;
    const int tid  = threadIdx.x;
    const int tr   = tid >> 4;
    const int tc   = tid & 15;

    float acc[8][8];
#pragma unroll
    for (int i = 0; i < 8; i++)
#pragma unroll
        for (int j = 0; j < 8; j++) acc[i][j] = 0.0f;

    float4 pa[2], pb[2];
#pragma unroll
    for (int it = 0; it < 2; it++) {
        int t  = tid + it * 256;
        int m  = t >> 2;
        int kq = (t & 3) << 2;
        int gr = row0 + m;
        pa[it] = (gr < n) ? *reinterpret_cast<const float4*>(&X[(size_t)gr * DIM + kq])
                          : make_float4(0.f, 0.f, 0.f, 0.f);
        pb[it] = __ldg(reinterpret_cast<const float4*>(&W[(size_t)m * DIM + kq]));
    }

    for (int k0 = 0; k0 < DIM; k0 += 16) {
#pragma unroll
        for (int it = 0; it < 2; it++) {
            int t  = tid + it * 256;
            int m  = t >> 2;
            int kq = (t & 3) << 2;
            As[kq + 0][m] = pa[it].x; As[kq + 1][m] = pa[it].y;
            As[kq + 2][m] = pa[it].z; As[kq + 3][m] = pa[it].w;
            Bs[kq + 0][m] = pb[it].x; Bs[kq + 1][m] = pb[it].y;
            Bs[kq + 2][m] = pb[it].z; Bs[kq + 3][m] = pb[it].w;
        }
        __syncthreads();

        if (k0 + 16 < DIM) {
#pragma unroll
            for (int it = 0; it < 2; it++) {
                int t  = tid + it * 256;
                int m  = t >> 2;
                int kq = (t & 3) << 2;
                int gr = row0 + m;
                pa[it] = (gr < n) ? *reinterpret_cast<const float4*>(&X[(size_t)gr * DIM + k0 + 16 + kq])
                                  : make_float4(0.f, 0.f, 0.f, 0.f);
                pb[it] = __ldg(reinterpret_cast<const float4*>(&W[(size_t)m * DIM + k0 + 16 + kq]));
            }
        }

#pragma unroll
        for (int k = 0; k < 16; k++) {
            float a[8], b[8];
            float4 a0 = *reinterpret_cast<const float4*>(&As[k][tr * 8]);
            float4 a1 = *reinterpret_cast<const float4*>(&As[k][tr * 8 + 4]);
            float4 b0 = *reinterpret_cast<const float4*>(&Bs[k][tc * 8]);
            float4 b1 = *reinterpret_cast<const float4*>(&Bs[k][tc * 8 + 4]);
            a[0]=a0.x; a[1]=a0.y; a[2]=a0.z; a[3]=a0.w;
            a[4]=a1.x; a[5]=a1.y; a[6]=a1.z; a[7]=a1.w;
            b[0]=b0.x; b[1]=b0.y; b[2]=b0.z; b[3]=b0.w;
            b[4]=b1.x; b[5]=b1.y; b[6]=b1.z; b[7]=b1.w;
#pragma unroll
            for (int i = 0; i < 8; i++)
#pragma unroll
                for (int j = 0; j < 8; j++) acc[i][j] += a[i] * b[j];
        }
        __syncthreads();
    }

    float bb[8];
#pragma unroll
    for (int j = 0; j < 8; j++) bb[j] = __ldg(&bias[tc * 8 + j]);
#pragma unroll
    for (int i = 0; i < 8; i++) {
        int gr = row0 + tr * 8 + i;
        if (gr < n) {
            float4 o0 = make_float4(acc[i][0] + bb[0], acc[i][1] + bb[1],
                                    acc[i][2] + bb[2], acc[i][3] + bb[3]);
            float4 o1 = make_float4(acc[i][4] + bb[4], acc[i][5] + bb[5],
                                    acc[i][6] + bb[6], acc[i][7] + bb[7]);
            *reinterpret_cast<float4*>(&Out[(size_t)gr * DIM + tc * 8])     = o0;
            *reinterpret_cast<float4*>(&Out[(size_t)gr * DIM + tc * 8 + 4]) = o1;
        }
    }
}

__global__ __launch_bounds__(256, 2)
void gemm_qkv_kernel(const float* __restrict__ x,
                     const float* __restrict__ Wq, const float* __restrict__ bq,
                     const float* __restrict__ Wk, const float* __restrict__ bk,
                     const float* __restrict__ Wv, const float* __restrict__ bv,
                     int n) {
    const float* W; const float* b; float* Out;
    if (blockIdx.y == 0)      { W = Wq; b = bq; Out = g_q; }
    else if (blockIdx.y == 1) { W = Wk; b = bk; Out = g_k; }
    else                      { W = Wv; b = bv; Out = g_v; }
    gemm_body(x, W, b, Out, n);
}

__global__ __launch_bounds__(256, 2)
void gemm_out_kernel(const float* __restrict__ Wo, const float* __restrict__ bo,
                     float* __restrict__ out, int n) {
    gemm_body(g_agg, Wo, bo, out, n);
}

// ---------------- fused attention: warp per target node ----------------
// k[tgt] held in registers; single pass over the node's (sorted) edges with
// online softmax; agg[tgt] written once, normalized. No atomics.
__global__ __launch_bounds__(256)
void attn_kernel(int n) {
    int node = (blockIdx.x * blockDim.x + threadIdx.x) >> 5;
    if (node >= n) return;
    int lane = threadIdx.x & 31;

    int start = g_start[node];
    int cnt   = g_cnt[node];

    // lane covers dims [lane*4, lane*4+4) => head h = lane>>2
    float4 kv = *reinterpret_cast<const float4*>(&g_k[(size_t)node * DIM + lane * 4]);

    float m = -FLT_MAX, sum = 0.0f;
    float ax = 0.f, ay = 0.f, az = 0.f, aw = 0.f;

    for (int base = 0; base < cnt; base += 32) {
        int myi = base + lane;
        int src_l = (myi < cnt) ? g_ssrc[start + myi] : 0;
        int lim = min(32, cnt - base);
        int j = 0;
        for (; j + 4 <= lim; j += 4) {
            float s[4]; float4 vv[4];
#pragma unroll
            for (int u = 0; u < 4; u++) {
                int src = __shfl_sync(FULLMASK, src_l, j + u);
                float4 qv = *reinterpret_cast<const float4*>(&g_q[(size_t)src * DIM + lane * 4]);
                vv[u]     = *reinterpret_cast<const float4*>(&g_v[(size_t)src * DIM + lane * 4]);
                float part = qv.x * kv.x + qv.y * kv.y + qv.z * kv.z + qv.w * kv.w;
                part += __shfl_xor_sync(FULLMASK, part, 1);
                part += __shfl_xor_sync(FULLMASK, part, 2);
                s[u] = part * 0.25f;    // 1/sqrt(HD=16)
            }
#pragma unroll
            for (int u = 0; u < 4; u++) {
                float nm = fmaxf(m, s[u]);
                float f  = __expf(m - nm);
                float p  = __expf(s[u] - nm);
                sum = sum * f + p;
                ax = ax * f + p * vv[u].x;
                ay = ay * f + p * vv[u].y;
                az = az * f + p * vv[u].z;
                aw = aw * f + p * vv[u].w;
                m = nm;
            }
        }
        for (; j < lim; j++) {
            int src = __shfl_sync(FULLMASK, src_l, j);
            float4 qv = *reinterpret_cast<const float4*>(&g_q[(size_t)src * DIM + lane * 4]);
            float4 vv = *reinterpret_cast<const float4*>(&g_v[(size_t)src * DIM + lane * 4]);
            float part = qv.x * kv.x + qv.y * kv.y + qv.z * kv.z + qv.w * kv.w;
            part += __shfl_xor_sync(FULLMASK, part, 1);
            part += __shfl_xor_sync(FULLMASK, part, 2);
            float s = part * 0.25f;
            float nm = fmaxf(m, s);
            float f  = __expf(m - nm);
            float p  = __expf(s - nm);
            sum = sum * f + p;
            ax = ax * f + p * vv.x;
            ay = ay * f + p * vv.y;
            az = az * f + p * vv.z;
            aw = aw * f + p * vv.w;
            m = nm;
        }
    }

    float inv = (sum > 0.0f) ? 1.0f / sum : 0.0f;
    float4 o = make_float4(ax * inv, ay * inv, az * inv, aw * inv);
    *reinterpret_cast<float4*>(&g_agg[(size_t)node * DIM + lane * 4]) = o;
}

// ---------------- launch ----------------
// Fork/join across two streams so the edge-sort chain overlaps the QKV GEMM.
// Streams/events are created once on the first call (the non-captured
// correctness run), so nothing is created while the harness captures.
static cudaStream_t s_side = nullptr;
static cudaEvent_t  s_ev_fork = nullptr, s_ev_join = nullptr;

extern "C" void kernel_launch(void* const* d_in, const int* in_sizes, int n_in,
                              void* d_out, int out_size) {
    const float* x    = (const float*)d_in[0];
    const void*  edge = d_in[1];
    const float* Wq   = (const float*)d_in[2];
    const float* bq   = (const float*)d_in[3];
    const float* Wk   = (const float*)d_in[4];
    const float* bk   = (const float*)d_in[5];
    const float* Wv   = (const float*)d_in[6];
    const float* bv   = (const float*)d_in[7];
    const float* Wo   = (const float*)d_in[8];
    const float* bo   = (const float*)d_in[9];
    float* out = (float*)d_out;

    int n = in_sizes[0] / DIM;
    int E = in_sizes[1] / 2;

    if (s_side == nullptr) {
        cudaStreamCreateWithFlags(&s_side, cudaStreamNonBlocking);
        cudaEventCreateWithFlags(&s_ev_fork, cudaEventDisableTiming);
        cudaEventCreateWithFlags(&s_ev_join, cudaEventDisableTiming);
    }

    int sblocks = (n + SCAN_BLK - 1) / SCAN_BLK;   // <= MAX_SBLOCKS

    // Fork: side stream runs the QKV GEMM while the default stream sorts edges.
    cudaEventRecord(s_ev_fork, 0);
    cudaStreamWaitEvent(s_side, s_ev_fork, 0);

    dim3 gqkv((n + 127) / 128, 3);
    gemm_qkv_kernel<<<gqkv, 256, 0, s_side>>>(x, Wq, bq, Wk, bk, Wv, bv, n);
    cudaEventRecord(s_ev_join, s_side);

    // Default stream: edge decode + counting sort by target.
    detect_kernel<<<1, 32>>>((const int*)edge);
    zero_cnt_kernel<<<(n + 256) / 256, 256>>>(n);
    prep_kernel<<<(E + 255) / 256, 256>>>(edge, E, n);
    scan1_kernel<<<sblocks, SCAN_BLK>>>(n);
    scan2_kernel<<<1, 64>>>(sblocks);
    scan3_kernel<<<sblocks, SCAN_BLK>>>(n);
    scatter_kernel<<<(E + 255) / 256, 256>>>(E, n);

    // Join: attention needs both q/k/v and the sorted edge lists.
    cudaStreamWaitEvent(0, s_ev_join, 0);

    attn_kernel<<<(n + 7) / 8, 256>>>(n);

    gemm_out_kernel<<<(n + 127) / 128, 256>>>(Wo, bo, out, n);
}

// round 12
// speedup vs baseline: 1.7529x; 1.0941x over previous
#include <cuda_runtime.h>
#include <cuda_fp16.h>
#include <cstdint>
#include <cfloat>

// Problem constants (fixed shapes per reference)
#define MAXN 50000
#define MAXE 800000
#define DIM  128
#define NH   8
#define HD   16
#define FULLMASK 0xFFFFFFFFu
#define SCAN_BLK 1024
#define MAX_SBLOCKS 64   // ceil(50000/1024)=49

// ---------------- scratch (no allocations allowed) ----------------
__device__ __align__(16) __half g_qh[MAXN * DIM];  // q in fp16 (attention gather)
__device__ __align__(16) float  g_k[MAXN * DIM];   // k in fp32 (read once per node)
__device__ __align__(16) __half g_vh[MAXN * DIM];  // v in fp16 (attention gather)
__device__ __align__(16) float  g_agg[MAXN * DIM];
__device__ int g_tgt[MAXE];
__device__ int g_src[MAXE];
__device__ int g_ssrc[MAXE];       // src ids sorted by tgt
__device__ int g_cnt[MAXN + 1];    // per-target degree
__device__ int g_start[MAXN + 1];  // exclusive prefix of cnt
__device__ int g_cur[MAXN + 1];    // scatter cursors
__device__ int g_bsum[MAX_SBLOCKS];
__device__ int g_boff[MAX_SBLOCKS];
__device__ int g_is64;             // edge_index dtype flag

// ---------------- dtype detection ----------------
// int64 little-endian buffer of values in [0, 50000): every odd 32-bit word of
// the first 128 words is zero. Genuine int32 index data matches that with
// probability ~(1/50000)^64 ~= 0.
__global__ void detect_kernel(const int* __restrict__ e32) {
    if (threadIdx.x == 0 && blockIdx.x == 0) {
        int allzero = 1;
        for (int i = 1; i < 128; i += 2)
            if (e32[i] != 0) { allzero = 0; break; }
        g_is64 = allzero;
    }
}

__global__ void zero_cnt_kernel(int n) {
    int i = blockIdx.x * blockDim.x + threadIdx.x;
    if (i <= n) g_cnt[i] = 0;
}

// ---------------- decode edges + histogram by target ----------------
__global__ __launch_bounds__(256)
void prep_kernel(const void* __restrict__ edge, int E, int n) {
    int e = blockIdx.x * blockDim.x + threadIdx.x;
    if (e >= E) return;
    int tgt, src;
    if (g_is64) {
        tgt = (int)__ldg(&((const long long*)edge)[e]);
        src = (int)__ldg(&((const long long*)edge)[E + e]);
    } else {
        tgt = __ldg(&((const int*)edge)[e]);
        src = __ldg(&((const int*)edge)[E + e]);
    }
    g_tgt[e] = tgt;
    g_src[e] = src;
    if ((unsigned)tgt < (unsigned)n && (unsigned)src < (unsigned)n)
        atomicAdd(&g_cnt[tgt], 1);
}

// ---------------- multi-block exclusive scan of g_cnt[0..n) ----------------
__global__ __launch_bounds__(SCAN_BLK)
void scan1_kernel(int n) {
    __shared__ int wsum[32];
    __shared__ int woff[32];
    int tid = threadIdx.x, lane = tid & 31, wid = tid >> 5;
    int i = blockIdx.x * SCAN_BLK + tid;
    int v = (i < n) ? g_cnt[i] : 0;
    int x = v;
#pragma unroll
    for (int off = 1; off < 32; off <<= 1) {
        int t = __shfl_up_sync(FULLMASK, x, off);
        if (lane >= off) x += t;
    }
    if (lane == 31) wsum[wid] = x;
    __syncthreads();
    if (wid == 0) {
        int w = wsum[lane];
        int y = w;
#pragma unroll
        for (int off = 1; off < 32; off <<= 1) {
            int t = __shfl_up_sync(FULLMASK, y, off);
            if (lane >= off) y += t;
        }
        woff[lane] = y - w;
        if (lane == 31) g_bsum[blockIdx.x] = y;
    }
    __syncthreads();
    if (i < n) g_start[i] = woff[wid] + x - v;
}

__global__ void scan2_kernel(int nblocks) {
    int lane = threadIdx.x;
    __shared__ int sh[MAX_SBLOCKS];
    if (lane < MAX_SBLOCKS) sh[lane] = (lane < nblocks) ? g_bsum[lane] : 0;
    __syncthreads();
    if (lane == 0) {
        int run = 0;
        for (int j = 0; j < nblocks; j++) { int t = sh[j]; sh[j] = run; run += t; }
    }
    __syncthreads();
    if (lane < nblocks) g_boff[lane] = sh[lane];
}

__global__ __launch_bounds__(SCAN_BLK)
void scan3_kernel(int n) {
    int i = blockIdx.x * SCAN_BLK + threadIdx.x;
    if (i < n) {
        int s = g_start[i] + g_boff[blockIdx.x];
        g_start[i] = s;
        g_cur[i]   = s;
    }
}

// ---------------- scatter edges into target-sorted order ----------------
__global__ __launch_bounds__(256)
void scatter_kernel(int E, int n) {
    int e = blockIdx.x * blockDim.x + threadIdx.x;
    if (e >= E) return;
    int tgt = g_tgt[e], src = g_src[e];
    if ((unsigned)tgt >= (unsigned)n || (unsigned)src >= (unsigned)n) return;
    int pos = atomicAdd(&g_cur[tgt], 1);
    g_ssrc[pos] = src;
}

// ---------------- SGEMM: Out[m][j] = sum_k X[m][k]*W[j][k] + b[j] ----------------
// BM=128, BN=128, BK=16, 256 threads, 8x8 micro-tile, register-prefetch
// double buffering. HALF_OUT selects fp16 vs fp32 output rows.
template <bool HALF_OUT>
__device__ __forceinline__ void gemm_body(const float* __restrict__ X,
                                          const float* __restrict__ W,
                                          const float* __restrict__ bias,
                                          void* __restrict__ OutV, int n) {
    __shared__ float As[16][128];   // As[k][m] = X[row0+m][k0+k]
    __shared__ float Bs[16][128];   // Bs[k][j] = W[j][k0+k]

    const int row0 = blockIdx.x * 128;
    const int tid  = threadIdx.x;
    const int tr   = tid >> 4;
    const int tc   = tid & 15;

    float acc[8][8];
#pragma unroll
    for (int i = 0; i < 8; i++)
#pragma unroll
        for (int j = 0; j < 8; j++) acc[i][j] = 0.0f;

    float4 pa[2], pb[2];
#pragma unroll
    for (int it = 0; it < 2; it++) {
        int t  = tid + it * 256;
        int m  = t >> 2;
        int kq = (t & 3) << 2;
        int gr = row0 + m;
        pa[it] = (gr < n) ? *reinterpret_cast<const float4*>(&X[(size_t)gr * DIM + kq])
                          : make_float4(0.f, 0.f, 0.f, 0.f);
        pb[it] = __ldg(reinterpret_cast<const float4*>(&W[(size_t)m * DIM + kq]));
    }

    for (int k0 = 0; k0 < DIM; k0 += 16) {
#pragma unroll
        for (int it = 0; it < 2; it++) {
            int t  = tid + it * 256;
            int m  = t >> 2;
            int kq = (t & 3) << 2;
            As[kq + 0][m] = pa[it].x; As[kq + 1][m] = pa[it].y;
            As[kq + 2][m] = pa[it].z; As[kq + 3][m] = pa[it].w;
            Bs[kq + 0][m] = pb[it].x; Bs[kq + 1][m] = pb[it].y;
            Bs[kq + 2][m] = pb[it].z; Bs[kq + 3][m] = pb[it].w;
        }
        __syncthreads();

        if (k0 + 16 < DIM) {
#pragma unroll
            for (int it = 0; it < 2; it++) {
                int t  = tid + it * 256;
                int m  = t >> 2;
                int kq = (t & 3) << 2;
                int gr = row0 + m;
                pa[it] = (gr < n) ? *reinterpret_cast<const float4*>(&X[(size_t)gr * DIM + k0 + 16 + kq])
                                  : make_float4(0.f, 0.f, 0.f, 0.f);
                pb[it] = __ldg(reinterpret_cast<const float4*>(&W[(size_t)m * DIM + k0 + 16 + kq]));
            }
        }

#pragma unroll
        for (int k = 0; k < 16; k++) {
            float a[8], b[8];
            float4 a0 = *reinterpret_cast<const float4*>(&As[k][tr * 8]);
            float4 a1 = *reinterpret_cast<const float4*>(&As[k][tr * 8 + 4]);
            float4 b0 = *reinterpret_cast<const float4*>(&Bs[k][tc * 8]);
            float4 b1 = *reinterpret_cast<const float4*>(&Bs[k][tc * 8 + 4]);
            a[0]=a0.x; a[1]=a0.y; a[2]=a0.z; a[3]=a0.w;
            a[4]=a1.x; a[5]=a1.y; a[6]=a1.z; a[7]=a1.w;
            b[0]=b0.x; b[1]=b0.y; b[2]=b0.z; b[3]=b0.w;
            b[4]=b1.x; b[5]=b1.y; b[6]=b1.z; b[7]=b1.w;
#pragma unroll
            for (int i = 0; i < 8; i++)
#pragma unroll
                for (int j = 0; j < 8; j++) acc[i][j] += a[i] * b[j];
        }
        __syncthreads();
    }

    float bb[8];
#pragma unroll
    for (int j = 0; j < 8; j++) bb[j] = __ldg(&bias[tc * 8 + j]);
#pragma unroll
    for (int i = 0; i < 8; i++) {
        int gr = row0 + tr * 8 + i;
        if (gr < n) {
            if (HALF_OUT) {
                __half2 h[4];
#pragma unroll
                for (int j = 0; j < 4; j++)
                    h[j] = __floats2half2_rn(acc[i][2 * j] + bb[2 * j],
                                             acc[i][2 * j + 1] + bb[2 * j + 1]);
                *reinterpret_cast<uint4*>(&((__half*)OutV)[(size_t)gr * DIM + tc * 8]) =
                    *reinterpret_cast<uint4*>(h);
            } else {
                float* Out = (float*)OutV;
                float4 o0 = make_float4(acc[i][0] + bb[0], acc[i][1] + bb[1],
                                        acc[i][2] + bb[2], acc[i][3] + bb[3]);
                float4 o1 = make_float4(acc[i][4] + bb[4], acc[i][5] + bb[5],
                                        acc[i][6] + bb[6], acc[i][7] + bb[7]);
                *reinterpret_cast<float4*>(&Out[(size_t)gr * DIM + tc * 8])     = o0;
                *reinterpret_cast<float4*>(&Out[(size_t)gr * DIM + tc * 8 + 4]) = o1;
            }
        }
    }
}

__global__ __launch_bounds__(256, 2)
void gemm_qkv_kernel(const float* __restrict__ x,
                     const float* __restrict__ Wq, const float* __restrict__ bq,
                     const float* __restrict__ Wk, const float* __restrict__ bk,
                     const float* __restrict__ Wv, const float* __restrict__ bv,
                     int n) {
    if (blockIdx.y == 0)      gemm_body<true >(x, Wq, bq, g_qh, n);
    else if (blockIdx.y == 1) gemm_body<false>(x, Wk, bk, g_k,  n);
    else                      gemm_body<true >(x, Wv, bv, g_vh, n);
}

__global__ __launch_bounds__(256, 2)
void gemm_out_kernel(const float* __restrict__ Wo, const float* __restrict__ bo,
                     float* __restrict__ out, int n) {
    gemm_body<false>(g_agg, Wo, bo, out, n);
}

// ---------------- fused attention: warp per target node ----------------
// k[tgt] (fp32) in registers; q/v gathered in fp16 (half the bytes); online
// softmax in fp32; agg[tgt] written once, normalized. No atomics.
__device__ __forceinline__ float4 load_h4(const __half* base, size_t off) {
    uint2 raw = *reinterpret_cast<const uint2*>(base + off);
    __half2 h0 = *reinterpret_cast<__half2*>(&raw.x);
    __half2 h1 = *reinterpret_cast<__half2*>(&raw.y);
    float2 f0 = __half22float2(h0);
    float2 f1 = __half22float2(h1);
    return make_float4(f0.x, f0.y, f1.x, f1.y);
}

__global__ __launch_bounds__(256)
void attn_kernel(int n) {
    int node = (blockIdx.x * blockDim.x + threadIdx.x) >> 5;
    if (node >= n) return;
    int lane = threadIdx.x & 31;

    int start = g_start[node];
    int cnt   = g_cnt[node];

    // lane covers dims [lane*4, lane*4+4) => head h = lane>>2
    float4 kv = *reinterpret_cast<const float4*>(&g_k[(size_t)node * DIM + lane * 4]);

    float m = -FLT_MAX, sum = 0.0f;
    float ax = 0.f, ay = 0.f, az = 0.f, aw = 0.f;

    for (int base = 0; base < cnt; base += 32) {
        int myi = base + lane;
        int src_l = (myi < cnt) ? g_ssrc[start + myi] : 0;
        int lim = min(32, cnt - base);
        int j = 0;
        for (; j + 4 <= lim; j += 4) {
            float s[4]; float4 vv[4];
#pragma unroll
            for (int u = 0; u < 4; u++) {
                int src = __shfl_sync(FULLMASK, src_l, j + u);
                float4 qv = load_h4(g_qh, (size_t)src * DIM + lane * 4);
                vv[u]     = load_h4(g_vh, (size_t)src * DIM + lane * 4);
                float part = qv.x * kv.x + qv.y * kv.y + qv.z * kv.z + qv.w * kv.w;
                part += __shfl_xor_sync(FULLMASK, part, 1);
                part += __shfl_xor_sync(FULLMASK, part, 2);
                s[u] = part * 0.25f;    // 1/sqrt(HD=16)
            }
#pragma unroll
            for (int u = 0; u < 4; u++) {
                float nm = fmaxf(m, s[u]);
                float f  = __expf(m - nm);
                float p  = __expf(s[u] - nm);
                sum = sum * f + p;
                ax = ax * f + p * vv[u].x;
                ay = ay * f + p * vv[u].y;
                az = az * f + p * vv[u].z;
                aw = aw * f + p * vv[u].w;
                m = nm;
            }
        }
        for (; j < lim; j++) {
            int src = __shfl_sync(FULLMASK, src_l, j);
            float4 qv = load_h4(g_qh, (size_t)src * DIM + lane * 4);
            float4 vv = load_h4(g_vh, (size_t)src * DIM + lane * 4);
            float part = qv.x * kv.x + qv.y * kv.y + qv.z * kv.z + qv.w * kv.w;
            part += __shfl_xor_sync(FULLMASK, part, 1);
            part += __shfl_xor_sync(FULLMASK, part, 2);
            float s = part * 0.25f;
            float nm = fmaxf(m, s);
            float f  = __expf(m - nm);
            float p  = __expf(s - nm);
            sum = sum * f + p;
            ax = ax * f + p * vv.x;
            ay = ay * f + p * vv.y;
            az = az * f + p * vv.z;
            aw = aw * f + p * vv.w;
            m = nm;
        }
    }

    float inv = (sum > 0.0f) ? 1.0f / sum : 0.0f;
    float4 o = make_float4(ax * inv, ay * inv, az * inv, aw * inv);
    *reinterpret_cast<float4*>(&g_agg[(size_t)node * DIM + lane * 4]) = o;
}

// ---------------- launch ----------------
// Fork/join across two streams so the edge-sort chain overlaps the QKV GEMM.
// Streams/events are created once on the first call (the non-captured
// correctness run), so nothing is created while the harness captures.
static cudaStream_t s_side = nullptr;
static cudaEvent_t  s_ev_fork = nullptr, s_ev_join = nullptr;

extern "C" void kernel_launch(void* const* d_in, const int* in_sizes, int n_in,
                              void* d_out, int out_size) {
    const float* x    = (const float*)d_in[0];
    const void*  edge = d_in[1];
    const float* Wq   = (const float*)d_in[2];
    const float* bq   = (const float*)d_in[3];
    const float* Wk   = (const float*)d_in[4];
    const float* bk   = (const float*)d_in[5];
    const float* Wv   = (const float*)d_in[6];
    const float* bv   = (const float*)d_in[7];
    const float* Wo   = (const float*)d_in[8];
    const float* bo   = (const float*)d_in[9];
    float* out = (float*)d_out;

    int n = in_sizes[0] / DIM;
    int E = in_sizes[1] / 2;

    if (s_side == nullptr) {
        cudaStreamCreateWithFlags(&s_side, cudaStreamNonBlocking);
        cudaEventCreateWithFlags(&s_ev_fork, cudaEventDisableTiming);
        cudaEventCreateWithFlags(&s_ev_join, cudaEventDisableTiming);
    }

    int sblocks = (n + SCAN_BLK - 1) / SCAN_BLK;   // <= MAX_SBLOCKS

    // Fork: side stream runs the QKV GEMM while the default stream sorts edges.
    cudaEventRecord(s_ev_fork, 0);
    cudaStreamWaitEvent(s_side, s_ev_fork, 0);

    dim3 gqkv((n + 127) / 128, 3);
    gemm_qkv_kernel<<<gqkv, 256, 0, s_side>>>(x, Wq, bq, Wk, bk, Wv, bv, n);
    cudaEventRecord(s_ev_join, s_side);

    // Default stream: edge decode + counting sort by target.
    detect_kernel<<<1, 32>>>((const int*)edge);
    zero_cnt_kernel<<<(n + 256) / 256, 256>>>(n);
    prep_kernel<<<(E + 255) / 256, 256>>>(edge, E, n);
    scan1_kernel<<<sblocks, SCAN_BLK>>>(n);
    scan2_kernel<<<1, 64>>>(sblocks);
    scan3_kernel<<<sblocks, SCAN_BLK>>>(n);
    scatter_kernel<<<(E + 255) / 256, 256>>>(E, n);

    // Join: attention needs both q/k/v and the sorted edge lists.
    cudaStreamWaitEvent(0, s_ev_join, 0);

    attn_kernel<<<(n + 7) / 8, 256>>>(n);

    gemm_out_kernel<<<(n + 127) / 128, 256>>>(Wo, bo, out, n);
}